// round 2
// baseline (speedup 1.0000x reference)
#include <cuda_runtime.h>
#include <cstdint>
#include <math.h>

// 3 stacked dilated LSTM layers (rates 1,2,4), T=512, B=128, H=D=256, fp32.
// Grid: 16 gate-blocks x 8 batch-blocks = 128 co-resident CTAs, 1/SM.
// Per-CTA: 64 gate rows x 16 batch, K=512, weights stationary in smem.

#define Hc    256
#define G4H   1024
#define BATCH 128
#define TT    512

#define WRS   562    // w row stride (words): 16 chunks*34 + pad
#define URS   562    // u row stride (words)
#define KCH   34     // stride per 32-k chunk (words)
#define PRS   18     // part row stride (words)
#define PPL   1152   // part plane stride (64*18)

__device__ float    g_h[2][512 * 256];
__device__ float    g_c[512 * 256];
__device__ unsigned g_bar[8];

__device__ __forceinline__ unsigned long long fma2(unsigned long long a,
                                                   unsigned long long b,
                                                   unsigned long long c) {
    unsigned long long d;
    asm("fma.rn.f32x2 %0, %1, %2, %3;" : "=l"(d) : "l"(a), "l"(b), "l"(c));
    return d;
}

__device__ __forceinline__ float pairsum(unsigned long long v) {
    unsigned lo_, hi_;
    asm("mov.b64 {%0, %1}, %2;" : "=r"(lo_), "=r"(hi_) : "l"(v));
    return __uint_as_float(lo_) + __uint_as_float(hi_);
}

__device__ __forceinline__ void bar_arrive(unsigned* p) {
    asm volatile("red.release.gpu.global.add.u32 [%0], 1;" :: "l"(p) : "memory");
}
__device__ __forceinline__ unsigned bar_peek(unsigned* p) {
    unsigned v;
    asm volatile("ld.acquire.gpu.global.u32 %0, [%1];" : "=r"(v) : "l"(p) : "memory");
    return v;
}

__device__ __forceinline__ float sigmoidf_(float x) {
    return 1.0f / (1.0f + expf(-x));
}

extern "C" __global__ void __launch_bounds__(256, 1)
drnn_layer(const float* __restrict__ input,   // (T,128,256)
           const float* __restrict__ Wih,     // (L,1024,256)
           const float* __restrict__ Whh,     // (L,1024,256)
           const float* __restrict__ bih,     // (L,1024)
           const float* __restrict__ bhh,     // (L,1024)
           float* __restrict__ out,           // (L,512,128,256)
           int layer, int rate, int Td, int Nper, int nSub, unsigned barBase)
{
    extern __shared__ float sm[];
    float* w_s    = sm;                       // 64 x WRS
    float* u_s    = w_s + 64 * WRS;           // 16 x URS
    float* part   = u_s + 16 * URS;           // 8 x PPL
    float* bias_s = part + 8 * PPL;           // 64

    const int g   = blockIdx.x;   // gate-block: h-cols [16g, 16g+16)
    const int nb  = blockIdx.y;   // batch-block
    const int tid = threadIdx.x;

    const float* WihL = Wih + (size_t)layer * G4H * Hc;
    const float* WhhL = Whh + (size_t)layer * G4H * Hc;

    // stationary weights: local row r = q*16+jl -> global row q*256 + g*16 + jl
    for (int idx = tid; idx < 64 * 512; idx += 256) {
        int r = idx >> 9;
        int k = idx & 511;
        int q  = r >> 4;
        int jl = r & 15;
        int R  = q * 256 + g * 16 + jl;
        float v = (k < 256) ? WihL[(size_t)R * 256 + k]
                            : WhhL[(size_t)R * 256 + (k - 256)];
        w_s[r * WRS + (k >> 5) * KCH + (k & 31)] = v;
    }
    if (tid < 64) {
        int q = tid >> 4, jl = tid & 15;
        int R = q * 256 + g * 16 + jl;
        bias_s[tid] = bih[layer * G4H + R] + bhh[layer * G4H + R];
    }
    __syncthreads();

    // thread roles
    const int t   = tid & 15;
    const int kq  = tid >> 4;     // k-split 0..15, pairs (2w,2w+1) share a warp
    const int gg  = t >> 1;       // row-lane 0..7  (rows gg, gg+8, ..., gg+56)
    const int cb  = t & 1;        // col-block 0..1 (cols cb*8 .. cb*8+7)
    const int pn  = tid >> 4;     // pointwise batch row
    const int pjl = tid & 15;     // pointwise h-col

    const float* wp = w_s + gg * WRS + kq * KCH;
    const float* up = u_s + (cb * 8) * URS + kq * KCH;

    unsigned* barp = &g_bar[nb];

    for (int s = 0; s < Td; ++s) {
        const float* hprev = g_h[(s + 1) & 1];
        float* hcur = g_h[s & 1];

        for (int sub = 0; sub < nSub; ++sub) {
            const int nG0 = nb * Nper + sub * 16;

            __syncthreads();   // part consumed / u free

            // ---- fill u[n][k] = [x_t ; h_{s-1}], chunked layout
            {
                int n  = tid >> 4;
                int l  = tid & 15;
                int nG = nG0 + n;
                int rr = nG >> 7;
                int bat = nG & 127;
                int time = s * rate + rr;
                float* ur = u_s + n * URS + l * KCH;
                if (l < 8) {
                    const float* src = input + ((size_t)time * BATCH + bat) * Hc + l * 32;
                    #pragma unroll
                    for (int kk = 0; kk < 32; kk += 4) {
                        float4 v = *(const float4*)(src + kk);
                        *(float2*)(ur + kk)     = make_float2(v.x, v.y);
                        *(float2*)(ur + kk + 2) = make_float2(v.z, v.w);
                    }
                } else {
                    const float* src = hprev + (size_t)nG * Hc + (l - 8) * 32;
                    #pragma unroll
                    for (int kk = 0; kk < 32; kk += 4) {
                        float4 v = (s == 0) ? make_float4(0.f, 0.f, 0.f, 0.f)
                                            : *(const float4*)(src + kk);
                        *(float2*)(ur + kk)     = make_float2(v.x, v.y);
                        *(float2*)(ur + kk + 2) = make_float2(v.z, v.w);
                    }
                }
            }
            __syncthreads();

            // ---- microkernel: 8x8 tile per thread, k-pairs via f32x2
            {
                unsigned long long acc[64];
                #pragma unroll
                for (int i = 0; i < 64; ++i) acc[i] = 0ULL;

                #pragma unroll 2
                for (int kk = 0; kk < 32; kk += 2) {
                    unsigned long long wv[8], uv[8];
                    #pragma unroll
                    for (int r = 0; r < 8; ++r)
                        wv[r] = *(const unsigned long long*)(wp + r * 8 * WRS + kk);
                    #pragma unroll
                    for (int c = 0; c < 8; ++c)
                        uv[c] = *(const unsigned long long*)(up + c * URS + kk);
                    #pragma unroll
                    for (int r = 0; r < 8; ++r)
                        #pragma unroll
                        for (int c = 0; c < 8; ++c)
                            acc[r * 8 + c] = fma2(wv[r], uv[c], acc[r * 8 + c]);
                }

                // pairsum + fold the two k-splits sharing this warp
                float sv[64];
                #pragma unroll
                for (int i = 0; i < 64; ++i) {
                    float v = pairsum(acc[i]);
                    v += __shfl_xor_sync(0xffffffffu, v, 16);
                    sv[i] = v;
                }

                if (!(kq & 1)) {
                    float* pp = part + (kq >> 1) * PPL + cb * 8;
                    #pragma unroll
                    for (int r = 0; r < 8; ++r) {
                        float* rp = pp + (gg + 8 * r) * PRS;
                        *(float2*)(rp + 0) = make_float2(sv[r*8+0], sv[r*8+1]);
                        *(float2*)(rp + 2) = make_float2(sv[r*8+2], sv[r*8+3]);
                        *(float2*)(rp + 4) = make_float2(sv[r*8+4], sv[r*8+5]);
                        *(float2*)(rp + 6) = make_float2(sv[r*8+6], sv[r*8+7]);
                    }
                }
            }
            __syncthreads();

            // ---- pointwise LSTM update
            {
                int n  = pn;
                int jl = pjl;
                int nG = nG0 + n;
                float gv[4];
                #pragma unroll
                for (int q = 0; q < 4; ++q) {
                    float v = bias_s[q * 16 + jl];
                    const float* pq = part + (q * 16 + jl) * PRS + n;
                    #pragma unroll
                    for (int w8 = 0; w8 < 8; ++w8) v += pq[w8 * PPL];
                    gv[q] = v;
                }
                float ig = sigmoidf_(gv[0]);
                float fg = sigmoidf_(gv[1]);
                float gt = tanhf(gv[2]);
                float og = sigmoidf_(gv[3]);

                int   jcol = g * 16 + jl;
                size_t sidx = (size_t)nG * Hc + jcol;
                float cold = (s == 0) ? 0.f : g_c[sidx];
                float cnew = fg * cold + ig * gt;
                float hnew = og * tanhf(cnew);
                g_c[sidx]  = cnew;
                hcur[sidx] = hnew;

                int rr   = nG >> 7;
                int bat  = nG & 127;
                int time = s * rate + rr;
                out[(((size_t)layer * TT + time) * BATCH + bat) * Hc + jcol] = hnew;
            }
        }

        // ---- barrier across the 16 gate-CTAs of this batch-block
        __threadfence();
        __syncthreads();
        if (tid == 0) {
            bar_arrive(barp);
            unsigned target = barBase + 16u * (unsigned)(s + 1);
            while (bar_peek(barp) < target) { }
        }
        __syncthreads();
    }
}

extern "C" void kernel_launch(void* const* d_in, const int* in_sizes, int n_in,
                              void* d_out, int out_size)
{
    const float* x   = (const float*)d_in[0];
    const float* Wih = (const float*)d_in[1];
    const float* Whh = (const float*)d_in[2];
    const float* bih = (const float*)d_in[3];
    const float* bhh = (const float*)d_in[4];
    float* out = (float*)d_out;

    const size_t smem = (size_t)(64 * WRS + 16 * URS + 8 * PPL + 64) * sizeof(float);
    cudaFuncSetAttribute(drnn_layer, cudaFuncAttributeMaxDynamicSharedMemorySize, (int)smem);

    void* barp = nullptr;
    cudaGetSymbolAddress(&barp, g_bar);
    cudaMemsetAsync(barp, 0, 8 * sizeof(unsigned), 0);

    dim3 grid(16, 8);
    const size_t layer_elems = (size_t)TT * BATCH * Hc;

    drnn_layer<<<grid, 256, smem>>>(x, Wih, Whh, bih, bhh, out,
                                    0, 1, 512, 16, 1, 0u);
    drnn_layer<<<grid, 256, smem>>>(out, Wih, Whh, bih, bhh, out,
                                    1, 2, 256, 32, 2, 16u * 512u);
    drnn_layer<<<grid, 256, smem>>>(out + layer_elems, Wih, Whh, bih, bhh, out,
                                    2, 4, 128, 64, 4, 16u * 768u);
}